// round 15
// baseline (speedup 1.0000x reference)
#include <cuda_runtime.h>
#include <cuda_bf16.h>
#include <cuda_fp16.h>
#include <cstdint>
#include <cstddef>

#define NN   8192
#define NWRD 256
#define NDC  64     // double-chunks of K=128

__device__ unsigned      g_bits[NN * NWRD];  // 8 MB adjacency bitmask
__device__ float         g_dinv[NN];
__device__ __nv_bfloat16 g_sbt[8 * NN];      // rows 0-3: hi(dinv_j*s_j), 4-7: lo
__device__ __half        g_yh[64 * NN];      // fp16 y' = dinv_j*(h1@W2), [e][j]

// ---------------- helpers ----------------
__device__ __forceinline__ uint32_t s2u(const void* p) {
    uint32_t a;
    asm("{ .reg .u64 t; cvta.to.shared.u64 t, %1; cvt.u32.u64 %0, t; }" : "=r"(a) : "l"(p));
    return a;
}
__device__ __forceinline__ uint32_t swz(uint32_t b) { return b ^ ((b >> 3) & 0x70); }
__device__ __forceinline__ void cpa16(uint32_t s, const void* g) {
    asm volatile("cp.async.cg.shared.global [%0], [%1], 16;" :: "r"(s), "l"(g) : "memory");
}
#define CP_COMMIT() asm volatile("cp.async.commit_group;" ::: "memory")
#define CP_WAIT(n)  asm volatile("cp.async.wait_group %0;" :: "n"(n) : "memory")

__device__ __forceinline__ uint4 lds128(uint32_t a) {
    uint4 v;
    asm("ld.shared.v4.b32 {%0,%1,%2,%3}, [%4];"
        : "=r"(v.x), "=r"(v.y), "=r"(v.z), "=r"(v.w) : "r"(a));
    return v;
}
__device__ __forceinline__ void ldmx4(uint32_t& r0, uint32_t& r1, uint32_t& r2, uint32_t& r3,
                                      uint32_t a) {
    asm volatile("ldmatrix.sync.aligned.m8n8.x4.shared.b16 {%0,%1,%2,%3}, [%4];"
                 : "=r"(r0), "=r"(r1), "=r"(r2), "=r"(r3) : "r"(a));
}
__device__ __forceinline__ void ldmx2(uint32_t& r0, uint32_t& r1, uint32_t a) {
    asm volatile("ldmatrix.sync.aligned.m8n8.x2.shared.b16 {%0,%1}, [%2];"
                 : "=r"(r0), "=r"(r1) : "r"(a));
}
__device__ __forceinline__ uint32_t lutbf(uint32_t p) {      // bf16 {0|1,0|1}
    return ((p & 1u) ? 0x3F80u : 0u) | ((p & 2u) ? 0x3F800000u : 0u);
}
__device__ __forceinline__ uint32_t luth(uint32_t p) {       // fp16 {0|1,0|1}
    return ((p & 1u) ? 0x3C00u : 0u) | ((p & 2u) ? 0x3C000000u : 0u);
}
__device__ __forceinline__ void mma16816(float* c, uint32_t a0, uint32_t a1, uint32_t a2,
                                         uint32_t a3, uint32_t b0, uint32_t b1) {
    asm volatile("mma.sync.aligned.m16n8k16.row.col.f32.bf16.bf16.f32 "
                 "{%0,%1,%2,%3}, {%4,%5,%6,%7}, {%8,%9}, {%0,%1,%2,%3};"
                 : "+f"(c[0]), "+f"(c[1]), "+f"(c[2]), "+f"(c[3])
                 : "r"(a0), "r"(a1), "r"(a2), "r"(a3), "r"(b0), "r"(b1));
}
__device__ __forceinline__ void mmah16(float* c, uint32_t a0, uint32_t a1, uint32_t a2,
                                       uint32_t a3, uint32_t b0, uint32_t b1) {
    asm volatile("mma.sync.aligned.m16n8k16.row.col.f32.f16.f16.f32 "
                 "{%0,%1,%2,%3}, {%4,%5,%6,%7}, {%8,%9}, {%0,%1,%2,%3};"
                 : "+f"(c[0]), "+f"(c[1]), "+f"(c[2]), "+f"(c[3])
                 : "r"(a0), "r"(a1), "r"(a2), "r"(a3), "r"(b0), "r"(b1));
}
// decode 4 A regs (one kk step) from two 64-bit row-words — bf16 variant
__device__ __forceinline__ void decA(uint2 wg, uint2 wg8, int kk, int tq,
                                     uint32_t& a0, uint32_t& a1, uint32_t& a2, uint32_t& a3) {
    const uint32_t w0 = (kk < 2) ? wg.x : wg.y;
    const uint32_t w1 = (kk < 2) ? wg8.x : wg8.y;
    const int sh = ((kk & 1) << 4) + (tq << 1);
    a0 = lutbf((w0 >> sh) & 3u);
    a1 = lutbf((w1 >> sh) & 3u);
    a2 = lutbf((w0 >> (sh + 8)) & 3u);
    a3 = lutbf((w1 >> (sh + 8)) & 3u);
}
// fp16 variant
__device__ __forceinline__ void decAh(uint2 wg, uint2 wg8, int kk, int tq,
                                      uint32_t& a0, uint32_t& a1, uint32_t& a2, uint32_t& a3) {
    const uint32_t w0 = (kk < 2) ? wg.x : wg.y;
    const uint32_t w1 = (kk < 2) ? wg8.x : wg8.y;
    const int sh = ((kk & 1) << 4) + (tq << 1);
    a0 = luth((w0 >> sh) & 3u);
    a1 = luth((w1 >> sh) & 3u);
    a2 = luth((w0 >> (sh + 8)) & 3u);
    a3 = luth((w1 >> (sh + 8)) & 3u);
}

// ============================================================
// kA: distances -> bitmask + dinv + s' hi/lo.  BALLOT version:
// lane l tests j = base + l; one ballot = one g_bits word (bit = j&31).
// ============================================================
__global__ void __launch_bounds__(256) kA(const float4* __restrict__ st) {
    extern __shared__ __align__(16) char smemA[];
    float2* spos = (float2*)smemA;
    int*    sdeg = (int*)(spos + NN);
    const int t = threadIdx.x, lane = t & 31, wid = t >> 5;

    for (int j = t; j < NN; j += 256) { float4 s = st[j]; spos[j] = make_float2(s.x, s.y); }
    if (t < 16) sdeg[t] = 0;
    __syncthreads();

    const int row0 = blockIdx.x << 4;

    for (int rq = 0; rq < 4; ++rq) {
        const int ib = row0 + (rq << 2);
        float xr[4], yr[4];
#pragma unroll
        for (int r = 0; r < 4; ++r) { xr[r] = spos[ib + r].x; yr[r] = spos[ib + r].y; }
        int cnt[4] = {0, 0, 0, 0};
        for (int c = 0; c < 8; ++c) {
#pragma unroll
            for (int q = 0; q < 4; ++q) {
                const int j = (c << 10) + (q << 8) + t;
                const float2 p = spos[j];
#pragma unroll
                for (int r = 0; r < 4; ++r) {
                    const float dx = xr[r] - p.x, dy = yr[r] - p.y;
                    const unsigned m = (dx * dx + dy * dy <= 1.0f);
                    const unsigned bal = __ballot_sync(0xffffffffu, m);
                    if (lane == 0) {
                        g_bits[(ib + r) * NWRD + (c << 5) + (q << 3) + wid] = bal;
                        cnt[r] += __popc(bal);
                    }
                }
            }
        }
        if (lane == 0) {
#pragma unroll
            for (int r = 0; r < 4; ++r) atomicAdd(&sdeg[(rq << 2) + r], cnt[r]);
        }
    }
    __syncthreads();

    if (t < 16) {
        const int i = row0 + t;
        const float dinv = rsqrtf((float)sdeg[t]);
        g_dinv[i] = dinv;
        float4 s = st[i];
        float v[4] = { dinv * s.x, dinv * s.y, dinv * s.z, dinv * s.w };
#pragma unroll
        for (int d = 0; d < 4; ++d) {
            __nv_bfloat16 hi = __float2bfloat16(v[d]);
            g_sbt[d * NN + i] = hi;
            g_sbt[(4 + d) * NN + i] = __float2bfloat16(v[d] - __bfloat162float(hi));
        }
    }
}

// ---------------- chunk loaders ----------------
// kG1 (256 thr): mask 1KB + B 2KB (bf16)
__device__ __forceinline__ void ldch1(int m0, int dc, uint32_t sM, uint32_t sB, int t) {
    if (t < 128) {
        int sub = t >> 6, rem = t & 63, row = rem >> 3, seg = rem & 7;
        cpa16(sB + sub * 1024 + swz(row * 128 + seg * 16),
              g_sbt + (size_t)row * NN + dc * 128 + sub * 64 + seg * 8);
    } else if (t < 192) {
        int row = t - 128;
        cpa16(sM + row * 16, g_bits + (size_t)(m0 + row) * NWRD + dc * 4);
    }
}
// kG2 GEMM (512 thr, M=64): mask 1KB + B 16KB (fp16, 64 rows, 2 sub-tiles)
__device__ __forceinline__ void ldch2(int m0, int dc, uint32_t sM, uint32_t sB, int t) {
    if (t < 64) cpa16(sM + t * 16, g_bits + (size_t)(m0 + t) * NWRD + dc * 4);
#pragma unroll
    for (int p = 0; p < 2; ++p) {
        int q = t + (p << 9);
        int sub = q >> 9, rem = q & 511, row = rem >> 3, seg = rem & 7;
        cpa16(sB + sub * 8192 + swz(row * 128 + seg * 16),
              g_yh + (size_t)row * NN + dc * 128 + sub * 64 + seg * 8);
    }
}

// ============================================================
// kG1: C[64x8] = A_tile @ [s'hi|s'lo]; split-K across warp halves; fused MLP.
// smem: mask 3x1KB @0, B 3x2KB @3072, w1 @9216, b1 @10240, w2 @10496, agg @26880
// ============================================================
__global__ void __launch_bounds__(256) kG1(const float* __restrict__ W1,
                                           const float* __restrict__ b1,
                                           const float* __restrict__ W2) {
    extern __shared__ __align__(16) char sm[];
    const uint32_t sb = s2u(sm);
    const int t = threadIdx.x, lane = t & 31, wid = t >> 5;
    const int g = lane >> 2, tq = lane & 3;
    const int h = wid >> 2, wr = wid & 3;
    const int m0 = blockIdx.x << 6;

    float* w1s = (float*)(sm + 9216);
    float* b1s = (float*)(sm + 10240);
    float* w2s = (float*)(sm + 10496);
    float* agg = (float*)(sm + 26880);   // [2][64][4]

    if (t < 256) w1s[t] = W1[t];
    if (t < 64)  b1s[t] = b1[t];
    for (int k = t; k < 4096; k += 256) w2s[k] = W2[k];

    const uint32_t MS = sb, BS = sb + 3072;
    const uint32_t lmbase = (lane & 7) * 128 + ((lane >> 3) & 1) * 16;

    float acc[4] = {0.f, 0.f, 0.f, 0.f};

#pragma unroll
    for (int s = 0; s < 2; ++s) { ldch1(m0, s, MS + s * 1024, BS + s * 2048, t); CP_COMMIT(); }

    for (int dc = 0; dc < NDC; ++dc) {
        const int s = dc % 3;
        CP_WAIT(1);
        __syncthreads();
        if (dc + 2 < NDC)
            ldch1(m0, dc + 2, MS + ((dc + 2) % 3) * 1024, BS + ((dc + 2) % 3) * 2048, t);
        CP_COMMIT();
        const uint32_t mS = MS + s * 1024;
        const uint32_t bsub = BS + s * 2048 + h * 1024;
        uint4 w0 = lds128(mS + (wr * 16 + g) * 16);
        uint4 w8 = lds128(mS + (wr * 16 + g + 8) * 16);
        uint2 wg  = h ? make_uint2(w0.z, w0.w) : make_uint2(w0.x, w0.y);
        uint2 wg8 = h ? make_uint2(w8.z, w8.w) : make_uint2(w8.x, w8.y);
#pragma unroll
        for (int kk = 0; kk < 4; ++kk) {
            uint32_t a0, a1, a2, a3, b0, b1r;
            decA(wg, wg8, kk, tq, a0, a1, a2, a3);
            ldmx2(b0, b1r, bsub + swz(lmbase + kk * 32));
            mma16816(acc, a0, a1, a2, a3, b0, b1r);
        }
    }
    CP_WAIT(0);

    {
        float s0 = acc[0] + __shfl_xor_sync(0xffffffffu, acc[0], 2);
        float s1 = acc[1] + __shfl_xor_sync(0xffffffffu, acc[1], 2);
        float s2 = acc[2] + __shfl_xor_sync(0xffffffffu, acc[2], 2);
        float s3 = acc[3] + __shfl_xor_sync(0xffffffffu, acc[3], 2);
        if (tq < 2) {
            const int row = wr * 16 + g;
            float* ag = agg + h * 256;
            ag[row * 4 + 2 * tq] = s0;
            ag[row * 4 + 2 * tq + 1] = s1;
            ag[(row + 8) * 4 + 2 * tq] = s2;
            ag[(row + 8) * 4 + 2 * tq + 1] = s3;
        }
    }
    __syncthreads();

    {
        const int r = t & 63, q = t >> 6, i = m0 + r;
        const float dinv = g_dinv[i];
        const float a0 = dinv * (agg[r * 4 + 0] + agg[256 + r * 4 + 0]);
        const float a1 = dinv * (agg[r * 4 + 1] + agg[256 + r * 4 + 1]);
        const float a2 = dinv * (agg[r * 4 + 2] + agg[256 + r * 4 + 2]);
        const float a3 = dinv * (agg[r * 4 + 3] + agg[256 + r * 4 + 3]);
        float hh[64];
#pragma unroll
        for (int k = 0; k < 64; ++k)
            hh[k] = fmaxf(b1s[k] + a0 * w1s[k] + a1 * w1s[64 + k]
                        + a2 * w1s[128 + k] + a3 * w1s[192 + k], 0.f);
        float y[16];
#pragma unroll
        for (int v = 0; v < 16; ++v) y[v] = 0.f;
        for (int k = 0; k < 64; ++k) {
            const float hk = hh[k];
            const float4* w4 = (const float4*)(w2s + k * 64 + q * 16);
#pragma unroll
            for (int v = 0; v < 4; ++v) {
                float4 w = w4[v];
                y[4 * v + 0] += hk * w.x;
                y[4 * v + 1] += hk * w.y;
                y[4 * v + 2] += hk * w.z;
                y[4 * v + 3] += hk * w.w;
            }
        }
#pragma unroll
        for (int v = 0; v < 16; ++v) {
            const int e = q * 16 + v;
            g_yh[e * NN + i] = __float2half(dinv * y[v]);
        }
    }
}

// ============================================================
// kG2 fused, parity-interleaved: even bid -> GEMM tile bid/2;
//                                 odd bid  -> mask expander bid/2.
// smem (GEMM only): mask 3x1KB @0, B 3x16KB @4096; Csm @4096, psum @20480
// ============================================================
__global__ void __launch_bounds__(512) kG2(const float* __restrict__ b2,
                                           const float* __restrict__ cw,
                                           const float* __restrict__ cb,
                                           float* __restrict__ dout,
                                           float* __restrict__ omask) {
    if (blockIdx.x & 1) {
        // ---------- mask expander ----------
        const int xb = blockIdx.x >> 1;                 // 0..127
        const int lane = threadIdx.x & 31, wid = threadIdx.x >> 5;
        const int gwarp = xb * 16 + wid;                // 0..2047
        for (int c = 0; c < 32; ++c) {
            const unsigned chunk = gwarp * 32 + c;      // 0..65535
            const unsigned wb = chunk * 32;
            const uint32_t w = g_bits[wb + lane];
            float4* dst = (float4*)(omask + (size_t)wb * 32);
#pragma unroll
            for (int m = 0; m < 8; ++m) {
                const uint32_t src = __shfl_sync(0xffffffffu, w, m * 4 + (lane >> 3));
                const uint32_t nib = (src >> ((lane & 7) * 4)) & 15u;
                float4 f;
                f.x = (nib & 1u) ? 1.f : 0.f;
                f.y = (nib & 2u) ? 1.f : 0.f;
                f.z = (nib & 4u) ? 1.f : 0.f;
                f.w = (nib & 8u) ? 1.f : 0.f;
                dst[m * 32 + lane] = f;
            }
        }
        return;
    }

    // ---------- GEMM (round-12 config, byte-identical math) ----------
    extern __shared__ __align__(16) char sm[];
    const uint32_t sb = s2u(sm);
    const int t = threadIdx.x, lane = t & 31, wid = t >> 5;
    const int g = lane >> 2, tq = lane & 3;
    const int wm = wid & 3, wn = wid >> 2;     // 4 m16-tiles x 4 n16-groups
    const int m0 = (blockIdx.x >> 1) << 6;

    const uint32_t MS = sb, BS = sb + 4096;
    uint32_t lmbase;
    {
        const int rsel = ((lane >> 4) & 1) * 8 + (lane & 7);
        const int kb16 = ((lane >> 3) & 1) * 16;
        lmbase = (uint32_t)((wn * 16 + rsel) * 128 + kb16);
    }

    float acc[2][4];
#pragma unroll
    for (int b = 0; b < 2; ++b)
#pragma unroll
        for (int c = 0; c < 4; ++c) acc[b][c] = 0.f;

#pragma unroll
    for (int s = 0; s < 2; ++s) { ldch2(m0, s, MS + s * 1024, BS + s * 16384, t); CP_COMMIT(); }

    for (int dc = 0; dc < NDC; ++dc) {
        const int s = dc % 3;
        CP_WAIT(1);
        __syncthreads();
        if (dc + 2 < NDC)
            ldch2(m0, dc + 2, MS + ((dc + 2) % 3) * 1024, BS + ((dc + 2) % 3) * 16384, t);
        CP_COMMIT();
        const uint32_t mS = MS + s * 1024, bS = BS + s * 16384;
        uint4 mw  = lds128(mS + (wm * 16 + g) * 16);
        uint4 mw8 = lds128(mS + (wm * 16 + g + 8) * 16);
#pragma unroll
        for (int sub = 0; sub < 2; ++sub) {
            const uint32_t bsub = bS + sub * 8192;
            uint2 wg  = sub ? make_uint2(mw.z, mw.w) : make_uint2(mw.x, mw.y);
            uint2 wg8 = sub ? make_uint2(mw8.z, mw8.w) : make_uint2(mw8.x, mw8.y);
#pragma unroll
            for (int kk = 0; kk < 4; ++kk) {
                uint32_t a0, a1, a2, a3, b00, b01, b10, b11;
                decAh(wg, wg8, kk, tq, a0, a1, a2, a3);
                ldmx4(b00, b01, b10, b11, bsub + swz(lmbase + kk * 32));
                mmah16(acc[0], a0, a1, a2, a3, b00, b01);
                mmah16(acc[1], a0, a1, a2, a3, b10, b11);
            }
        }
    }
    CP_WAIT(0);
    __syncthreads();

    float* Csm = (float*)(sm + 4096);   // [64][64] f32
#pragma unroll
    for (int bn = 0; bn < 2; ++bn) {
        const int row = wm * 16 + g;
        const int col = wn * 16 + bn * 8 + 2 * tq;
        Csm[row * 64 + col]           = acc[bn][0];
        Csm[row * 64 + col + 1]       = acc[bn][1];
        Csm[(row + 8) * 64 + col]     = acc[bn][2];
        Csm[(row + 8) * 64 + col + 1] = acc[bn][3];
    }
    float* psum = (float*)(sm + 20480);   // [8][64]
    __syncthreads();
    {
        const int r = t & 63, q = t >> 6;
        const float dinv = g_dinv[m0 + r];
        float p = 0.f;
#pragma unroll
        for (int v = 0; v < 8; ++v) {
            const int d = q * 8 + v;
            float hh = fmaxf(dinv * Csm[r * 64 + d] + b2[d], 0.f);
            p += hh * cw[d];
        }
        psum[q * 64 + r] = p;
    }
    __syncthreads();
    if (t < 64) {
        float p = psum[t] + psum[64 + t] + psum[128 + t] + psum[192 + t]
                + psum[256 + t] + psum[320 + t] + psum[384 + t] + psum[448 + t];
        dout[m0 + t] = p + cb[0];
    }
}

// ============================================================
extern "C" void kernel_launch(void* const* d_in, const int* in_sizes, int n_in,
                              void* d_out, int out_size) {
    const float* states = (const float*)d_in[0];
    const float* W1 = (const float*)d_in[1];
    const float* b1 = (const float*)d_in[2];
    const float* W2 = (const float*)d_in[3];
    const float* b2 = (const float*)d_in[4];
    const float* cw = (const float*)d_in[5];
    const float* cb = (const float*)d_in[6];
    float* out = (float*)d_out;

    const int smemA  = NN * (int)sizeof(float2) + 64;
    const int smemG1 = 28928;
    const int smemG2 = 4096 + 3 * 16384;   // 53248

    cudaFuncSetAttribute(kA,  cudaFuncAttributeMaxDynamicSharedMemorySize, smemA);
    cudaFuncSetAttribute(kG1, cudaFuncAttributeMaxDynamicSharedMemorySize, smemG1);
    cudaFuncSetAttribute(kG2, cudaFuncAttributeMaxDynamicSharedMemorySize, smemG2);

    kA<<<512, 256, smemA>>>((const float4*)states);
    kG1<<<128, 256, smemG1>>>(W1, b1, W2);
    kG2<<<256, 512, smemG2>>>(b2, cw, cb, out, out + NN);
}

// round 16
// speedup vs baseline: 1.0003x; 1.0003x over previous
#include <cuda_runtime.h>
#include <cuda_bf16.h>
#include <cuda_fp16.h>
#include <cstdint>
#include <cstddef>

#define NN   8192
#define NWRD 256
#define NDC  64     // double-chunks of K=128
#define GEMM_CTAS 128

__device__ unsigned      g_bits[NN * NWRD];  // 8 MB adjacency bitmask
__device__ float         g_dinv[NN];
__device__ __nv_bfloat16 g_sbt[8 * NN];      // rows 0-3: hi(dinv_j*s_j), 4-7: lo
__device__ __half        g_yh[64 * NN];      // fp16 y' = dinv_j*(h1@W2), [e][j]

// ---------------- helpers ----------------
__device__ __forceinline__ uint32_t s2u(const void* p) {
    uint32_t a;
    asm("{ .reg .u64 t; cvta.to.shared.u64 t, %1; cvt.u32.u64 %0, t; }" : "=r"(a) : "l"(p));
    return a;
}
__device__ __forceinline__ uint32_t swz(uint32_t b) { return b ^ ((b >> 3) & 0x70); }
__device__ __forceinline__ void cpa16(uint32_t s, const void* g) {
    asm volatile("cp.async.cg.shared.global [%0], [%1], 16;" :: "r"(s), "l"(g) : "memory");
}
#define CP_COMMIT() asm volatile("cp.async.commit_group;" ::: "memory")
#define CP_WAIT(n)  asm volatile("cp.async.wait_group %0;" :: "n"(n) : "memory")

__device__ __forceinline__ uint4 lds128(uint32_t a) {
    uint4 v;
    asm("ld.shared.v4.b32 {%0,%1,%2,%3}, [%4];"
        : "=r"(v.x), "=r"(v.y), "=r"(v.z), "=r"(v.w) : "r"(a));
    return v;
}
__device__ __forceinline__ void ldmx4(uint32_t& r0, uint32_t& r1, uint32_t& r2, uint32_t& r3,
                                      uint32_t a) {
    asm volatile("ldmatrix.sync.aligned.m8n8.x4.shared.b16 {%0,%1,%2,%3}, [%4];"
                 : "=r"(r0), "=r"(r1), "=r"(r2), "=r"(r3) : "r"(a));
}
__device__ __forceinline__ void ldmx2(uint32_t& r0, uint32_t& r1, uint32_t a) {
    asm volatile("ldmatrix.sync.aligned.m8n8.x2.shared.b16 {%0,%1}, [%2];"
                 : "=r"(r0), "=r"(r1) : "r"(a));
}
__device__ __forceinline__ uint32_t lutbf(uint32_t p) {      // bf16 {0|1,0|1}
    return ((p & 1u) ? 0x3F80u : 0u) | ((p & 2u) ? 0x3F800000u : 0u);
}
__device__ __forceinline__ uint32_t luth(uint32_t p) {       // fp16 {0|1,0|1}
    return ((p & 1u) ? 0x3C00u : 0u) | ((p & 2u) ? 0x3C000000u : 0u);
}
__device__ __forceinline__ void mma16816(float* c, uint32_t a0, uint32_t a1, uint32_t a2,
                                         uint32_t a3, uint32_t b0, uint32_t b1) {
    asm volatile("mma.sync.aligned.m16n8k16.row.col.f32.bf16.bf16.f32 "
                 "{%0,%1,%2,%3}, {%4,%5,%6,%7}, {%8,%9}, {%0,%1,%2,%3};"
                 : "+f"(c[0]), "+f"(c[1]), "+f"(c[2]), "+f"(c[3])
                 : "r"(a0), "r"(a1), "r"(a2), "r"(a3), "r"(b0), "r"(b1));
}
__device__ __forceinline__ void mmah16(float* c, uint32_t a0, uint32_t a1, uint32_t a2,
                                       uint32_t a3, uint32_t b0, uint32_t b1) {
    asm volatile("mma.sync.aligned.m16n8k16.row.col.f32.f16.f16.f32 "
                 "{%0,%1,%2,%3}, {%4,%5,%6,%7}, {%8,%9}, {%0,%1,%2,%3};"
                 : "+f"(c[0]), "+f"(c[1]), "+f"(c[2]), "+f"(c[3])
                 : "r"(a0), "r"(a1), "r"(a2), "r"(a3), "r"(b0), "r"(b1));
}
// decode 4 A regs (one kk step) from two 64-bit row-words — bf16 variant
__device__ __forceinline__ void decA(uint2 wg, uint2 wg8, int kk, int tq,
                                     uint32_t& a0, uint32_t& a1, uint32_t& a2, uint32_t& a3) {
    const uint32_t w0 = (kk < 2) ? wg.x : wg.y;
    const uint32_t w1 = (kk < 2) ? wg8.x : wg8.y;
    const int sh = ((kk & 1) << 4) + (tq << 1);
    a0 = lutbf((w0 >> sh) & 3u);
    a1 = lutbf((w1 >> sh) & 3u);
    a2 = lutbf((w0 >> (sh + 8)) & 3u);
    a3 = lutbf((w1 >> (sh + 8)) & 3u);
}
// fp16 variant
__device__ __forceinline__ void decAh(uint2 wg, uint2 wg8, int kk, int tq,
                                      uint32_t& a0, uint32_t& a1, uint32_t& a2, uint32_t& a3) {
    const uint32_t w0 = (kk < 2) ? wg.x : wg.y;
    const uint32_t w1 = (kk < 2) ? wg8.x : wg8.y;
    const int sh = ((kk & 1) << 4) + (tq << 1);
    a0 = luth((w0 >> sh) & 3u);
    a1 = luth((w1 >> sh) & 3u);
    a2 = luth((w0 >> (sh + 8)) & 3u);
    a3 = luth((w1 >> (sh + 8)) & 3u);
}

// ============================================================
// kA: distances -> bitmask + dinv + s' hi/lo.  BALLOT version (validated R15):
// lane l tests j = base + l; one ballot = one g_bits word (bit = j&31).
// ============================================================
__global__ void __launch_bounds__(256) kA(const float4* __restrict__ st) {
    extern __shared__ __align__(16) char smemA[];
    float2* spos = (float2*)smemA;
    int*    sdeg = (int*)(spos + NN);
    const int t = threadIdx.x, lane = t & 31, wid = t >> 5;

    for (int j = t; j < NN; j += 256) { float4 s = st[j]; spos[j] = make_float2(s.x, s.y); }
    if (t < 16) sdeg[t] = 0;
    __syncthreads();

    const int row0 = blockIdx.x << 4;

    for (int rq = 0; rq < 4; ++rq) {
        const int ib = row0 + (rq << 2);
        float xr[4], yr[4];
#pragma unroll
        for (int r = 0; r < 4; ++r) { xr[r] = spos[ib + r].x; yr[r] = spos[ib + r].y; }
        int cnt[4] = {0, 0, 0, 0};
        for (int c = 0; c < 8; ++c) {
#pragma unroll
            for (int q = 0; q < 4; ++q) {
                const int j = (c << 10) + (q << 8) + t;
                const float2 p = spos[j];
#pragma unroll
                for (int r = 0; r < 4; ++r) {
                    const float dx = xr[r] - p.x, dy = yr[r] - p.y;
                    const unsigned m = (dx * dx + dy * dy <= 1.0f);
                    const unsigned bal = __ballot_sync(0xffffffffu, m);
                    if (lane == 0) {
                        g_bits[(ib + r) * NWRD + (c << 5) + (q << 3) + wid] = bal;
                        cnt[r] += __popc(bal);
                    }
                }
            }
        }
        if (lane == 0) {
#pragma unroll
            for (int r = 0; r < 4; ++r) atomicAdd(&sdeg[(rq << 2) + r], cnt[r]);
        }
    }
    __syncthreads();

    if (t < 16) {
        const int i = row0 + t;
        const float dinv = rsqrtf((float)sdeg[t]);
        g_dinv[i] = dinv;
        float4 s = st[i];
        float v[4] = { dinv * s.x, dinv * s.y, dinv * s.z, dinv * s.w };
#pragma unroll
        for (int d = 0; d < 4; ++d) {
            __nv_bfloat16 hi = __float2bfloat16(v[d]);
            g_sbt[d * NN + i] = hi;
            g_sbt[(4 + d) * NN + i] = __float2bfloat16(v[d] - __bfloat162float(hi));
        }
    }
}

// ---------------- chunk loaders ----------------
// kG1 (256 thr): mask 1KB + B 2KB (bf16)
__device__ __forceinline__ void ldch1(int m0, int dc, uint32_t sM, uint32_t sB, int t) {
    if (t < 128) {
        int sub = t >> 6, rem = t & 63, row = rem >> 3, seg = rem & 7;
        cpa16(sB + sub * 1024 + swz(row * 128 + seg * 16),
              g_sbt + (size_t)row * NN + dc * 128 + sub * 64 + seg * 8);
    } else if (t < 192) {
        int row = t - 128;
        cpa16(sM + row * 16, g_bits + (size_t)(m0 + row) * NWRD + dc * 4);
    }
}
// kG2 GEMM (512 thr, M=64): mask 1KB + B 16KB (fp16, 64 rows, 2 sub-tiles)
__device__ __forceinline__ void ldch2(int m0, int dc, uint32_t sM, uint32_t sB, int t) {
    if (t < 64) cpa16(sM + t * 16, g_bits + (size_t)(m0 + t) * NWRD + dc * 4);
#pragma unroll
    for (int p = 0; p < 2; ++p) {
        int q = t + (p << 9);
        int sub = q >> 9, rem = q & 511, row = rem >> 3, seg = rem & 7;
        cpa16(sB + sub * 8192 + swz(row * 128 + seg * 16),
              g_yh + (size_t)row * NN + dc * 128 + sub * 64 + seg * 8);
    }
}

// ============================================================
// kG1: C[64x8] = A_tile @ [s'hi|s'lo]; split-K across warp halves; fused MLP.
// smem: mask 3x1KB @0, B 3x2KB @3072, w1 @9216, b1 @10240, w2 @10496, agg @26880
// ============================================================
__global__ void __launch_bounds__(256) kG1(const float* __restrict__ W1,
                                           const float* __restrict__ b1,
                                           const float* __restrict__ W2) {
    extern __shared__ __align__(16) char sm[];
    const uint32_t sb = s2u(sm);
    const int t = threadIdx.x, lane = t & 31, wid = t >> 5;
    const int g = lane >> 2, tq = lane & 3;
    const int h = wid >> 2, wr = wid & 3;
    const int m0 = blockIdx.x << 6;

    float* w1s = (float*)(sm + 9216);
    float* b1s = (float*)(sm + 10240);
    float* w2s = (float*)(sm + 10496);
    float* agg = (float*)(sm + 26880);   // [2][64][4]

    if (t < 256) w1s[t] = W1[t];
    if (t < 64)  b1s[t] = b1[t];
    for (int k = t; k < 4096; k += 256) w2s[k] = W2[k];

    const uint32_t MS = sb, BS = sb + 3072;
    const uint32_t lmbase = (lane & 7) * 128 + ((lane >> 3) & 1) * 16;

    float acc[4] = {0.f, 0.f, 0.f, 0.f};

#pragma unroll
    for (int s = 0; s < 2; ++s) { ldch1(m0, s, MS + s * 1024, BS + s * 2048, t); CP_COMMIT(); }

    for (int dc = 0; dc < NDC; ++dc) {
        const int s = dc % 3;
        CP_WAIT(1);
        __syncthreads();
        if (dc + 2 < NDC)
            ldch1(m0, dc + 2, MS + ((dc + 2) % 3) * 1024, BS + ((dc + 2) % 3) * 2048, t);
        CP_COMMIT();
        const uint32_t mS = MS + s * 1024;
        const uint32_t bsub = BS + s * 2048 + h * 1024;
        uint4 w0 = lds128(mS + (wr * 16 + g) * 16);
        uint4 w8 = lds128(mS + (wr * 16 + g + 8) * 16);
        uint2 wg  = h ? make_uint2(w0.z, w0.w) : make_uint2(w0.x, w0.y);
        uint2 wg8 = h ? make_uint2(w8.z, w8.w) : make_uint2(w8.x, w8.y);
#pragma unroll
        for (int kk = 0; kk < 4; ++kk) {
            uint32_t a0, a1, a2, a3, b0, b1r;
            decA(wg, wg8, kk, tq, a0, a1, a2, a3);
            ldmx2(b0, b1r, bsub + swz(lmbase + kk * 32));
            mma16816(acc, a0, a1, a2, a3, b0, b1r);
        }
    }
    CP_WAIT(0);

    {
        float s0 = acc[0] + __shfl_xor_sync(0xffffffffu, acc[0], 2);
        float s1 = acc[1] + __shfl_xor_sync(0xffffffffu, acc[1], 2);
        float s2 = acc[2] + __shfl_xor_sync(0xffffffffu, acc[2], 2);
        float s3 = acc[3] + __shfl_xor_sync(0xffffffffu, acc[3], 2);
        if (tq < 2) {
            const int row = wr * 16 + g;
            float* ag = agg + h * 256;
            ag[row * 4 + 2 * tq] = s0;
            ag[row * 4 + 2 * tq + 1] = s1;
            ag[(row + 8) * 4 + 2 * tq] = s2;
            ag[(row + 8) * 4 + 2 * tq + 1] = s3;
        }
    }
    __syncthreads();

    {
        const int r = t & 63, q = t >> 6, i = m0 + r;
        const float dinv = g_dinv[i];
        const float a0 = dinv * (agg[r * 4 + 0] + agg[256 + r * 4 + 0]);
        const float a1 = dinv * (agg[r * 4 + 1] + agg[256 + r * 4 + 1]);
        const float a2 = dinv * (agg[r * 4 + 2] + agg[256 + r * 4 + 2]);
        const float a3 = dinv * (agg[r * 4 + 3] + agg[256 + r * 4 + 3]);
        float hh[64];
#pragma unroll
        for (int k = 0; k < 64; ++k)
            hh[k] = fmaxf(b1s[k] + a0 * w1s[k] + a1 * w1s[64 + k]
                        + a2 * w1s[128 + k] + a3 * w1s[192 + k], 0.f);
        float y[16];
#pragma unroll
        for (int v = 0; v < 16; ++v) y[v] = 0.f;
        for (int k = 0; k < 64; ++k) {
            const float hk = hh[k];
            const float4* w4 = (const float4*)(w2s + k * 64 + q * 16);
#pragma unroll
            for (int v = 0; v < 4; ++v) {
                float4 w = w4[v];
                y[4 * v + 0] += hk * w.x;
                y[4 * v + 1] += hk * w.y;
                y[4 * v + 2] += hk * w.z;
                y[4 * v + 3] += hk * w.w;
            }
        }
#pragma unroll
        for (int v = 0; v < 16; ++v) {
            const int e = q * 16 + v;
            g_yh[e * NN + i] = __float2half(dinv * y[v]);
        }
    }
}

// ============================================================
// kG2 fused (round-14 ordering): blocks [0,128) GEMM; blocks [128,384)
// are 256 HALF-SIZE mask expanders (finer tail load-balance).
// smem (GEMM only): mask 3x1KB @0, B 3x16KB @4096; Csm @4096, psum @20480
// ============================================================
__global__ void __launch_bounds__(512) kG2(const float* __restrict__ b2,
                                           const float* __restrict__ cw,
                                           const float* __restrict__ cb,
                                           float* __restrict__ dout,
                                           float* __restrict__ omask) {
    if (blockIdx.x >= GEMM_CTAS) {
        // ---------- mask expander: 256 CTAs x 16 warps x 16 chunks ----------
        const int xb = blockIdx.x - GEMM_CTAS;          // 0..255
        const int lane = threadIdx.x & 31, wid = threadIdx.x >> 5;
        const int gwarp = xb * 16 + wid;                // 0..4095
        for (int c = 0; c < 16; ++c) {
            const unsigned chunk = gwarp * 16 + c;      // 0..65535
            const unsigned wb = chunk * 32;
            const uint32_t w = g_bits[wb + lane];
            float4* dst = (float4*)(omask + (size_t)wb * 32);
#pragma unroll
            for (int m = 0; m < 8; ++m) {
                const uint32_t src = __shfl_sync(0xffffffffu, w, m * 4 + (lane >> 3));
                const uint32_t nib = (src >> ((lane & 7) * 4)) & 15u;
                float4 f;
                f.x = (nib & 1u) ? 1.f : 0.f;
                f.y = (nib & 2u) ? 1.f : 0.f;
                f.z = (nib & 4u) ? 1.f : 0.f;
                f.w = (nib & 8u) ? 1.f : 0.f;
                dst[m * 32 + lane] = f;
            }
        }
        return;
    }

    // ---------- GEMM (round-12 config, byte-identical math) ----------
    extern __shared__ __align__(16) char sm[];
    const uint32_t sb = s2u(sm);
    const int t = threadIdx.x, lane = t & 31, wid = t >> 5;
    const int g = lane >> 2, tq = lane & 3;
    const int wm = wid & 3, wn = wid >> 2;     // 4 m16-tiles x 4 n16-groups
    const int m0 = blockIdx.x << 6;

    const uint32_t MS = sb, BS = sb + 4096;
    uint32_t lmbase;
    {
        const int rsel = ((lane >> 4) & 1) * 8 + (lane & 7);
        const int kb16 = ((lane >> 3) & 1) * 16;
        lmbase = (uint32_t)((wn * 16 + rsel) * 128 + kb16);
    }

    float acc[2][4];
#pragma unroll
    for (int b = 0; b < 2; ++b)
#pragma unroll
        for (int c = 0; c < 4; ++c) acc[b][c] = 0.f;

#pragma unroll
    for (int s = 0; s < 2; ++s) { ldch2(m0, s, MS + s * 1024, BS + s * 16384, t); CP_COMMIT(); }

    for (int dc = 0; dc < NDC; ++dc) {
        const int s = dc % 3;
        CP_WAIT(1);
        __syncthreads();
        if (dc + 2 < NDC)
            ldch2(m0, dc + 2, MS + ((dc + 2) % 3) * 1024, BS + ((dc + 2) % 3) * 16384, t);
        CP_COMMIT();
        const uint32_t mS = MS + s * 1024, bS = BS + s * 16384;
        uint4 mw  = lds128(mS + (wm * 16 + g) * 16);
        uint4 mw8 = lds128(mS + (wm * 16 + g + 8) * 16);
#pragma unroll
        for (int sub = 0; sub < 2; ++sub) {
            const uint32_t bsub = bS + sub * 8192;
            uint2 wg  = sub ? make_uint2(mw.z, mw.w) : make_uint2(mw.x, mw.y);
            uint2 wg8 = sub ? make_uint2(mw8.z, mw8.w) : make_uint2(mw8.x, mw8.y);
#pragma unroll
            for (int kk = 0; kk < 4; ++kk) {
                uint32_t a0, a1, a2, a3, b00, b01, b10, b11;
                decAh(wg, wg8, kk, tq, a0, a1, a2, a3);
                ldmx4(b00, b01, b10, b11, bsub + swz(lmbase + kk * 32));
                mmah16(acc[0], a0, a1, a2, a3, b00, b01);
                mmah16(acc[1], a0, a1, a2, a3, b10, b11);
            }
        }
    }
    CP_WAIT(0);
    __syncthreads();

    float* Csm = (float*)(sm + 4096);   // [64][64] f32
#pragma unroll
    for (int bn = 0; bn < 2; ++bn) {
        const int row = wm * 16 + g;
        const int col = wn * 16 + bn * 8 + 2 * tq;
        Csm[row * 64 + col]           = acc[bn][0];
        Csm[row * 64 + col + 1]       = acc[bn][1];
        Csm[(row + 8) * 64 + col]     = acc[bn][2];
        Csm[(row + 8) * 64 + col + 1] = acc[bn][3];
    }
    float* psum = (float*)(sm + 20480);   // [8][64]
    __syncthreads();
    {
        const int r = t & 63, q = t >> 6;
        const float dinv = g_dinv[m0 + r];
        float p = 0.f;
#pragma unroll
        for (int v = 0; v < 8; ++v) {
            const int d = q * 8 + v;
            float hh = fmaxf(dinv * Csm[r * 64 + d] + b2[d], 0.f);
            p += hh * cw[d];
        }
        psum[q * 64 + r] = p;
    }
    __syncthreads();
    if (t < 64) {
        float p = psum[t] + psum[64 + t] + psum[128 + t] + psum[192 + t]
                + psum[256 + t] + psum[320 + t] + psum[384 + t] + psum[448 + t];
        dout[m0 + t] = p + cb[0];
    }
}

// ============================================================
extern "C" void kernel_launch(void* const* d_in, const int* in_sizes, int n_in,
                              void* d_out, int out_size) {
    const float* states = (const float*)d_in[0];
    const float* W1 = (const float*)d_in[1];
    const float* b1 = (const float*)d_in[2];
    const float* W2 = (const float*)d_in[3];
    const float* b2 = (const float*)d_in[4];
    const float* cw = (const float*)d_in[5];
    const float* cb = (const float*)d_in[6];
    float* out = (float*)d_out;

    const int smemA  = NN * (int)sizeof(float2) + 64;
    const int smemG1 = 28928;
    const int smemG2 = 4096 + 3 * 16384;   // 53248

    cudaFuncSetAttribute(kA,  cudaFuncAttributeMaxDynamicSharedMemorySize, smemA);
    cudaFuncSetAttribute(kG1, cudaFuncAttributeMaxDynamicSharedMemorySize, smemG1);
    cudaFuncSetAttribute(kG2, cudaFuncAttributeMaxDynamicSharedMemorySize, smemG2);

    kA<<<512, 256, smemA>>>((const float4*)states);
    kG1<<<128, 256, smemG1>>>(W1, b1, W2);
    kG2<<<384, 512, smemG2>>>(b2, cw, cb, out, out + NN);
}

// round 17
// speedup vs baseline: 1.2806x; 1.2802x over previous
#include <cuda_runtime.h>
#include <cuda_bf16.h>
#include <cuda_fp16.h>
#include <cstdint>
#include <cstddef>

#define NN   8192
#define NWRD 256
#define NDC  64     // double-chunks of K=128
#define GEMM_CTAS 128

__device__ unsigned      g_bits[NN * NWRD];  // 8 MB adjacency bitmask
__device__ float         g_dinv[NN];
__device__ __nv_bfloat16 g_sbt[8 * NN];      // rows 0-3: hi(dinv_j*s_j), 4-7: lo
__device__ __half        g_yh[64 * NN];      // fp16 y' = dinv_j*(h1@W2), [e][j]

// ---------------- helpers ----------------
__device__ __forceinline__ uint32_t s2u(const void* p) {
    uint32_t a;
    asm("{ .reg .u64 t; cvta.to.shared.u64 t, %1; cvt.u32.u64 %0, t; }" : "=r"(a) : "l"(p));
    return a;
}
__device__ __forceinline__ uint32_t swz(uint32_t b) { return b ^ ((b >> 3) & 0x70); }
__device__ __forceinline__ void cpa16(uint32_t s, const void* g) {
    asm volatile("cp.async.cg.shared.global [%0], [%1], 16;" :: "r"(s), "l"(g) : "memory");
}
#define CP_COMMIT() asm volatile("cp.async.commit_group;" ::: "memory")
#define CP_WAIT(n)  asm volatile("cp.async.wait_group %0;" :: "n"(n) : "memory")

__device__ __forceinline__ uint4 lds128(uint32_t a) {
    uint4 v;
    asm("ld.shared.v4.b32 {%0,%1,%2,%3}, [%4];"
        : "=r"(v.x), "=r"(v.y), "=r"(v.z), "=r"(v.w) : "r"(a));
    return v;
}
__device__ __forceinline__ void ldmx4(uint32_t& r0, uint32_t& r1, uint32_t& r2, uint32_t& r3,
                                      uint32_t a) {
    asm volatile("ldmatrix.sync.aligned.m8n8.x4.shared.b16 {%0,%1,%2,%3}, [%4];"
                 : "=r"(r0), "=r"(r1), "=r"(r2), "=r"(r3) : "r"(a));
}
__device__ __forceinline__ void ldmx2(uint32_t& r0, uint32_t& r1, uint32_t a) {
    asm volatile("ldmatrix.sync.aligned.m8n8.x2.shared.b16 {%0,%1}, [%2];"
                 : "=r"(r0), "=r"(r1) : "r"(a));
}
__device__ __forceinline__ uint32_t lutbf(uint32_t p) {      // bf16 {0|1,0|1}
    return ((p & 1u) ? 0x3F80u : 0u) | ((p & 2u) ? 0x3F800000u : 0u);
}
__device__ __forceinline__ uint32_t luth(uint32_t p) {       // fp16 {0|1,0|1}
    return ((p & 1u) ? 0x3C00u : 0u) | ((p & 2u) ? 0x3C000000u : 0u);
}
__device__ __forceinline__ void stgcs4(float* p, float4 f) {
    asm volatile("st.global.cs.v4.f32 [%0], {%1,%2,%3,%4};"
                 :: "l"(p), "f"(f.x), "f"(f.y), "f"(f.z), "f"(f.w) : "memory");
}
__device__ __forceinline__ void mma16816(float* c, uint32_t a0, uint32_t a1, uint32_t a2,
                                         uint32_t a3, uint32_t b0, uint32_t b1) {
    asm volatile("mma.sync.aligned.m16n8k16.row.col.f32.bf16.bf16.f32 "
                 "{%0,%1,%2,%3}, {%4,%5,%6,%7}, {%8,%9}, {%0,%1,%2,%3};"
                 : "+f"(c[0]), "+f"(c[1]), "+f"(c[2]), "+f"(c[3])
                 : "r"(a0), "r"(a1), "r"(a2), "r"(a3), "r"(b0), "r"(b1));
}
__device__ __forceinline__ void mmah16(float* c, uint32_t a0, uint32_t a1, uint32_t a2,
                                       uint32_t a3, uint32_t b0, uint32_t b1) {
    asm volatile("mma.sync.aligned.m16n8k16.row.col.f32.f16.f16.f32 "
                 "{%0,%1,%2,%3}, {%4,%5,%6,%7}, {%8,%9}, {%0,%1,%2,%3};"
                 : "+f"(c[0]), "+f"(c[1]), "+f"(c[2]), "+f"(c[3])
                 : "r"(a0), "r"(a1), "r"(a2), "r"(a3), "r"(b0), "r"(b1));
}
// decode 4 A regs (one kk step) from two 64-bit row-words — bf16 variant
__device__ __forceinline__ void decA(uint2 wg, uint2 wg8, int kk, int tq,
                                     uint32_t& a0, uint32_t& a1, uint32_t& a2, uint32_t& a3) {
    const uint32_t w0 = (kk < 2) ? wg.x : wg.y;
    const uint32_t w1 = (kk < 2) ? wg8.x : wg8.y;
    const int sh = ((kk & 1) << 4) + (tq << 1);
    a0 = lutbf((w0 >> sh) & 3u);
    a1 = lutbf((w1 >> sh) & 3u);
    a2 = lutbf((w0 >> (sh + 8)) & 3u);
    a3 = lutbf((w1 >> (sh + 8)) & 3u);
}
// fp16 variant
__device__ __forceinline__ void decAh(uint2 wg, uint2 wg8, int kk, int tq,
                                      uint32_t& a0, uint32_t& a1, uint32_t& a2, uint32_t& a3) {
    const uint32_t w0 = (kk < 2) ? wg.x : wg.y;
    const uint32_t w1 = (kk < 2) ? wg8.x : wg8.y;
    const int sh = ((kk & 1) << 4) + (tq << 1);
    a0 = luth((w0 >> sh) & 3u);
    a1 = luth((w1 >> sh) & 3u);
    a2 = luth((w0 >> (sh + 8)) & 3u);
    a3 = luth((w1 >> (sh + 8)) & 3u);
}

// ============================================================
// kA: distances -> bitmask + dinv + s' hi/lo (round-14 shfl version)
// ============================================================
__global__ void __launch_bounds__(256) kA(const float4* __restrict__ st) {
    extern __shared__ __align__(16) char smemA[];
    float2* spos = (float2*)smemA;
    int*    sdeg = (int*)(spos + NN);
    const int t = threadIdx.x, lane = t & 31;

    for (int j = t; j < NN; j += 256) { float4 s = st[j]; spos[j] = make_float2(s.x, s.y); }
    if (t < 16) sdeg[t] = 0;
    __syncthreads();

    const int row0 = blockIdx.x << 4;
    const float4* sp4 = (const float4*)spos;

    for (int rq = 0; rq < 4; ++rq) {
        const int ib = row0 + (rq << 2);
        float xr[4], yr[4];
#pragma unroll
        for (int q = 0; q < 4; ++q) { xr[q] = spos[ib + q].x; yr[q] = spos[ib + q].y; }
        int cnt[4] = {0, 0, 0, 0};
#pragma unroll
        for (int c = 0; c < 8; ++c) {
            const int j = (c << 10) + (t << 2);
            float4 p01 = sp4[j >> 1], p23 = sp4[(j >> 1) + 1];
#pragma unroll
            for (int q = 0; q < 4; ++q) {
                float dx0 = xr[q] - p01.x, dy0 = yr[q] - p01.y;
                float dx1 = xr[q] - p01.z, dy1 = yr[q] - p01.w;
                float dx2 = xr[q] - p23.x, dy2 = yr[q] - p23.y;
                float dx3 = xr[q] - p23.z, dy3 = yr[q] - p23.w;
                unsigned m0 = (dx0 * dx0 + dy0 * dy0 <= 1.0f);
                unsigned m1 = (dx1 * dx1 + dy1 * dy1 <= 1.0f);
                unsigned m2 = (dx2 * dx2 + dy2 * dy2 <= 1.0f);
                unsigned m3 = (dx3 * dx3 + dy3 * dy3 <= 1.0f);
                unsigned nib = m0 | (m1 << 1) | (m2 << 2) | (m3 << 3);
                cnt[q] += (int)(m0 + m1 + m2 + m3);
                unsigned v = nib << ((lane & 7) * 4);
                v |= __shfl_xor_sync(0xffffffffu, v, 1);
                v |= __shfl_xor_sync(0xffffffffu, v, 2);
                v |= __shfl_xor_sync(0xffffffffu, v, 4);
                if ((lane & 7) == 0) {
                    const int jb = (c << 10) + ((t >> 5) << 7);
                    g_bits[(ib + q) * NWRD + (jb >> 5) + (lane >> 3)] = v;
                }
            }
        }
#pragma unroll
        for (int q = 0; q < 4; ++q) {
#pragma unroll
            for (int o = 16; o; o >>= 1) cnt[q] += __shfl_xor_sync(0xffffffffu, cnt[q], o);
            if (lane == 0) atomicAdd(&sdeg[(rq << 2) + q], cnt[q]);
        }
    }
    __syncthreads();

    if (t < 16) {
        const int i = row0 + t;
        const float dinv = rsqrtf((float)sdeg[t]);
        g_dinv[i] = dinv;
        float4 s = st[i];
        float v[4] = { dinv * s.x, dinv * s.y, dinv * s.z, dinv * s.w };
#pragma unroll
        for (int d = 0; d < 4; ++d) {
            __nv_bfloat16 hi = __float2bfloat16(v[d]);
            g_sbt[d * NN + i] = hi;
            g_sbt[(4 + d) * NN + i] = __float2bfloat16(v[d] - __bfloat162float(hi));
        }
    }
}

// ---------------- chunk loaders ----------------
// kG1 (256 thr): mask 1KB + B 2KB (bf16)
__device__ __forceinline__ void ldch1(int m0, int dc, uint32_t sM, uint32_t sB, int t) {
    if (t < 128) {
        int sub = t >> 6, rem = t & 63, row = rem >> 3, seg = rem & 7;
        cpa16(sB + sub * 1024 + swz(row * 128 + seg * 16),
              g_sbt + (size_t)row * NN + dc * 128 + sub * 64 + seg * 8);
    } else if (t < 192) {
        int row = t - 128;
        cpa16(sM + row * 16, g_bits + (size_t)(m0 + row) * NWRD + dc * 4);
    }
}
// kG2 GEMM (512 thr, M=64): mask 1KB + B 16KB (fp16, 64 rows, 2 sub-tiles)
__device__ __forceinline__ void ldch2(int m0, int dc, uint32_t sM, uint32_t sB, int t) {
    if (t < 64) cpa16(sM + t * 16, g_bits + (size_t)(m0 + t) * NWRD + dc * 4);
#pragma unroll
    for (int p = 0; p < 2; ++p) {
        int q = t + (p << 9);
        int sub = q >> 9, rem = q & 511, row = rem >> 3, seg = rem & 7;
        cpa16(sB + sub * 8192 + swz(row * 128 + seg * 16),
              g_yh + (size_t)row * NN + dc * 128 + sub * 64 + seg * 8);
    }
}

// ============================================================
// kG1: C[64x8] = A_tile @ [s'hi|s'lo]; split-K across warp halves; fused MLP.
// smem: mask 3x1KB @0, B 3x2KB @3072, w1 @9216, b1 @10240, w2 @10496, agg @26880
// ============================================================
__global__ void __launch_bounds__(256) kG1(const float* __restrict__ W1,
                                           const float* __restrict__ b1,
                                           const float* __restrict__ W2) {
    extern __shared__ __align__(16) char sm[];
    const uint32_t sb = s2u(sm);
    const int t = threadIdx.x, lane = t & 31, wid = t >> 5;
    const int g = lane >> 2, tq = lane & 3;
    const int h = wid >> 2, wr = wid & 3;
    const int m0 = blockIdx.x << 6;

    float* w1s = (float*)(sm + 9216);
    float* b1s = (float*)(sm + 10240);
    float* w2s = (float*)(sm + 10496);
    float* agg = (float*)(sm + 26880);   // [2][64][4]

    if (t < 256) w1s[t] = W1[t];
    if (t < 64)  b1s[t] = b1[t];
    for (int k = t; k < 4096; k += 256) w2s[k] = W2[k];

    const uint32_t MS = sb, BS = sb + 3072;
    const uint32_t lmbase = (lane & 7) * 128 + ((lane >> 3) & 1) * 16;

    float acc[4] = {0.f, 0.f, 0.f, 0.f};

#pragma unroll
    for (int s = 0; s < 2; ++s) { ldch1(m0, s, MS + s * 1024, BS + s * 2048, t); CP_COMMIT(); }

    for (int dc = 0; dc < NDC; ++dc) {
        const int s = dc % 3;
        CP_WAIT(1);
        __syncthreads();
        if (dc + 2 < NDC)
            ldch1(m0, dc + 2, MS + ((dc + 2) % 3) * 1024, BS + ((dc + 2) % 3) * 2048, t);
        CP_COMMIT();
        const uint32_t mS = MS + s * 1024;
        const uint32_t bsub = BS + s * 2048 + h * 1024;
        uint4 w0 = lds128(mS + (wr * 16 + g) * 16);
        uint4 w8 = lds128(mS + (wr * 16 + g + 8) * 16);
        uint2 wg  = h ? make_uint2(w0.z, w0.w) : make_uint2(w0.x, w0.y);
        uint2 wg8 = h ? make_uint2(w8.z, w8.w) : make_uint2(w8.x, w8.y);
#pragma unroll
        for (int kk = 0; kk < 4; ++kk) {
            uint32_t a0, a1, a2, a3, b0, b1r;
            decA(wg, wg8, kk, tq, a0, a1, a2, a3);
            ldmx2(b0, b1r, bsub + swz(lmbase + kk * 32));
            mma16816(acc, a0, a1, a2, a3, b0, b1r);
        }
    }
    CP_WAIT(0);

    {
        float s0 = acc[0] + __shfl_xor_sync(0xffffffffu, acc[0], 2);
        float s1 = acc[1] + __shfl_xor_sync(0xffffffffu, acc[1], 2);
        float s2 = acc[2] + __shfl_xor_sync(0xffffffffu, acc[2], 2);
        float s3 = acc[3] + __shfl_xor_sync(0xffffffffu, acc[3], 2);
        if (tq < 2) {
            const int row = wr * 16 + g;
            float* ag = agg + h * 256;
            ag[row * 4 + 2 * tq] = s0;
            ag[row * 4 + 2 * tq + 1] = s1;
            ag[(row + 8) * 4 + 2 * tq] = s2;
            ag[(row + 8) * 4 + 2 * tq + 1] = s3;
        }
    }
    __syncthreads();

    {
        const int r = t & 63, q = t >> 6, i = m0 + r;
        const float dinv = g_dinv[i];
        const float a0 = dinv * (agg[r * 4 + 0] + agg[256 + r * 4 + 0]);
        const float a1 = dinv * (agg[r * 4 + 1] + agg[256 + r * 4 + 1]);
        const float a2 = dinv * (agg[r * 4 + 2] + agg[256 + r * 4 + 2]);
        const float a3 = dinv * (agg[r * 4 + 3] + agg[256 + r * 4 + 3]);
        float hh[64];
#pragma unroll
        for (int k = 0; k < 64; ++k)
            hh[k] = fmaxf(b1s[k] + a0 * w1s[k] + a1 * w1s[64 + k]
                        + a2 * w1s[128 + k] + a3 * w1s[192 + k], 0.f);
        float y[16];
#pragma unroll
        for (int v = 0; v < 16; ++v) y[v] = 0.f;
        for (int k = 0; k < 64; ++k) {
            const float hk = hh[k];
            const float4* w4 = (const float4*)(w2s + k * 64 + q * 16);
#pragma unroll
            for (int v = 0; v < 4; ++v) {
                float4 w = w4[v];
                y[4 * v + 0] += hk * w.x;
                y[4 * v + 1] += hk * w.y;
                y[4 * v + 2] += hk * w.z;
                y[4 * v + 3] += hk * w.w;
            }
        }
#pragma unroll
        for (int v = 0; v < 16; ++v) {
            const int e = q * 16 + v;
            g_yh[e * NN + i] = __float2half(dinv * y[v]);
        }
    }
}

// ============================================================
// kG2 fused (round-14 structure): blocks [0,128) GEMM; blocks [128,256)
// mask expanders (st.global.cs streaming stores — the ONLY delta vs R14).
// smem (GEMM only): mask 3x1KB @0, B 3x16KB @4096; Csm @4096, psum @20480
// ============================================================
__global__ void __launch_bounds__(512) kG2(const float* __restrict__ b2,
                                           const float* __restrict__ cw,
                                           const float* __restrict__ cb,
                                           float* __restrict__ dout,
                                           float* __restrict__ omask) {
    if (blockIdx.x >= GEMM_CTAS) {
        // ---------- mask expander ----------
        const int xb = blockIdx.x - GEMM_CTAS;          // 0..127
        const int lane = threadIdx.x & 31, wid = threadIdx.x >> 5;
        const int gwarp = xb * 16 + wid;                // 0..2047
        for (int c = 0; c < 32; ++c) {
            const unsigned chunk = gwarp * 32 + c;      // 0..65535
            const unsigned wb = chunk * 32;
            const uint32_t w = g_bits[wb + lane];
            float* dst = omask + (size_t)wb * 32;
#pragma unroll
            for (int m = 0; m < 8; ++m) {
                const uint32_t src = __shfl_sync(0xffffffffu, w, m * 4 + (lane >> 3));
                const uint32_t nib = (src >> ((lane & 7) * 4)) & 15u;
                float4 f;
                f.x = (nib & 1u) ? 1.f : 0.f;
                f.y = (nib & 2u) ? 1.f : 0.f;
                f.z = (nib & 4u) ? 1.f : 0.f;
                f.w = (nib & 8u) ? 1.f : 0.f;
                stgcs4(dst + (m * 32 + lane) * 4, f);
            }
        }
        return;
    }

    // ---------- GEMM (round-12 config, byte-identical math) ----------
    extern __shared__ __align__(16) char sm[];
    const uint32_t sb = s2u(sm);
    const int t = threadIdx.x, lane = t & 31, wid = t >> 5;
    const int g = lane >> 2, tq = lane & 3;
    const int wm = wid & 3, wn = wid >> 2;     // 4 m16-tiles x 4 n16-groups
    const int m0 = blockIdx.x << 6;

    const uint32_t MS = sb, BS = sb + 4096;
    uint32_t lmbase;
    {
        const int rsel = ((lane >> 4) & 1) * 8 + (lane & 7);
        const int kb16 = ((lane >> 3) & 1) * 16;
        lmbase = (uint32_t)((wn * 16 + rsel) * 128 + kb16);
    }

    float acc[2][4];
#pragma unroll
    for (int b = 0; b < 2; ++b)
#pragma unroll
        for (int c = 0; c < 4; ++c) acc[b][c] = 0.f;

#pragma unroll
    for (int s = 0; s < 2; ++s) { ldch2(m0, s, MS + s * 1024, BS + s * 16384, t); CP_COMMIT(); }

    for (int dc = 0; dc < NDC; ++dc) {
        const int s = dc % 3;
        CP_WAIT(1);
        __syncthreads();
        if (dc + 2 < NDC)
            ldch2(m0, dc + 2, MS + ((dc + 2) % 3) * 1024, BS + ((dc + 2) % 3) * 16384, t);
        CP_COMMIT();
        const uint32_t mS = MS + s * 1024, bS = BS + s * 16384;
        uint4 mw  = lds128(mS + (wm * 16 + g) * 16);
        uint4 mw8 = lds128(mS + (wm * 16 + g + 8) * 16);
#pragma unroll
        for (int sub = 0; sub < 2; ++sub) {
            const uint32_t bsub = bS + sub * 8192;
            uint2 wg  = sub ? make_uint2(mw.z, mw.w) : make_uint2(mw.x, mw.y);
            uint2 wg8 = sub ? make_uint2(mw8.z, mw8.w) : make_uint2(mw8.x, mw8.y);
#pragma unroll
            for (int kk = 0; kk < 4; ++kk) {
                uint32_t a0, a1, a2, a3, b00, b01, b10, b11;
                decAh(wg, wg8, kk, tq, a0, a1, a2, a3);
                ldmx4(b00, b01, b10, b11, bsub + swz(lmbase + kk * 32));
                mmah16(acc[0], a0, a1, a2, a3, b00, b01);
                mmah16(acc[1], a0, a1, a2, a3, b10, b11);
            }
        }
    }
    CP_WAIT(0);
    __syncthreads();

    float* Csm = (float*)(sm + 4096);   // [64][64] f32
#pragma unroll
    for (int bn = 0; bn < 2; ++bn) {
        const int row = wm * 16 + g;
        const int col = wn * 16 + bn * 8 + 2 * tq;
        Csm[row * 64 + col]           = acc[bn][0];
        Csm[row * 64 + col + 1]       = acc[bn][1];
        Csm[(row + 8) * 64 + col]     = acc[bn][2];
        Csm[(row + 8) * 64 + col + 1] = acc[bn][3];
    }
    float* psum = (float*)(sm + 20480);   // [8][64]
    __syncthreads();
    {
        const int r = t & 63, q = t >> 6;
        const float dinv = g_dinv[m0 + r];
        float p = 0.f;
#pragma unroll
        for (int v = 0; v < 8; ++v) {
            const int d = q * 8 + v;
            float hh = fmaxf(dinv * Csm[r * 64 + d] + b2[d], 0.f);
            p += hh * cw[d];
        }
        psum[q * 64 + r] = p;
    }
    __syncthreads();
    if (t < 64) {
        float p = psum[t] + psum[64 + t] + psum[128 + t] + psum[192 + t]
                + psum[256 + t] + psum[320 + t] + psum[384 + t] + psum[448 + t];
        dout[m0 + t] = p + cb[0];
    }
}

// ============================================================
extern "C" void kernel_launch(void* const* d_in, const int* in_sizes, int n_in,
                              void* d_out, int out_size) {
    const float* states = (const float*)d_in[0];
    const float* W1 = (const float*)d_in[1];
    const float* b1 = (const float*)d_in[2];
    const float* W2 = (const float*)d_in[3];
    const float* b2 = (const float*)d_in[4];
    const float* cw = (const float*)d_in[5];
    const float* cb = (const float*)d_in[6];
    float* out = (float*)d_out;

    const int smemA  = NN * (int)sizeof(float2) + 64;
    const int smemG1 = 28928;
    const int smemG2 = 4096 + 3 * 16384;   // 53248

    cudaFuncSetAttribute(kA,  cudaFuncAttributeMaxDynamicSharedMemorySize, smemA);
    cudaFuncSetAttribute(kG1, cudaFuncAttributeMaxDynamicSharedMemorySize, smemG1);
    cudaFuncSetAttribute(kG2, cudaFuncAttributeMaxDynamicSharedMemorySize, smemG2);

    kA<<<512, 256, smemA>>>((const float4*)states);
    kG1<<<128, 256, smemG1>>>(W1, b1, W2);
    kG2<<<256, 512, smemG2>>>(b2, cw, cb, out, out + NN);
}